// round 4
// baseline (speedup 1.0000x reference)
#include <cuda_runtime.h>
#include <math.h>

// Problem constants: generated [2, 3, 96, 96]
#define B       2
#define NPIX    9216            // 96*96
#define TOTQ    (B * NPIX)      // 18432 queries
#define K       8               // NUM_CLUSTERS
#define NTHR    256
#define QPB     512             // queries per CTA (256 thr x 2)
#define NQG     (NPIX / QPB)    // 18 query groups per batch

// Phase 1: threshold from a uniform 1/8 sample (stride 8), 4 subchunks
#define SSTRIDE 8
#define SAMP    (NPIX / SSTRIDE)   // 1152 sample candidates
#define NSC     4
#define SSZ     (SAMP / NSC)       // 288 per subchunk

// Phase 2: full scan in 8 chunks
#define NCHUNK  8
#define CHUNK   (NPIX / NCHUNK)    // 1152

#define NMERGE  (TOTQ / NTHR)      // 72 merge blocks

typedef unsigned long long u64;

// Device scratch (allocation-free rule: __device__ globals)
__device__ ulonglong2 g_cand2[B * NPIX * 2];   // {-2x,-2x},{-2y,-2y},{-2z,-2z},{c2,c2}
__device__ float      g_tpart[NSC * K][TOTQ];  // phase-1 partial top-8 (scores)
__device__ float      g_thr[TOTQ];             // per-query threshold (score space)
__device__ float      g_part[NCHUNK * K][TOTQ];// phase-2 partial top-8 (d^2)
__device__ float      g_bsum[NMERGE];
__device__ unsigned   g_ticket;                // zero-initialized; reset after use

// ---- packed helpers: only fma.rn.f32x2 is available in PTX on this build --
__device__ __forceinline__ u64 fma2(u64 a, u64 b, u64 c) {
    u64 d;
    asm("fma.rn.f32x2 %0, %1, %2, %3;" : "=l"(d) : "l"(a), "l"(b), "l"(c));
    return d;
}
__device__ __forceinline__ u64 pack2(float lo, float hi) {
    u64 d;
    asm("mov.b64 %0, {%1, %2};" : "=l"(d) : "f"(lo), "f"(hi));
    return d;
}
__device__ __forceinline__ float2 unpack2(u64 v) {
    float2 r;
    asm("mov.b64 {%0, %1}, %2;" : "=f"(r.x), "=f"(r.y) : "l"(v));
    return r;
}

// Scalar compare-exchange insert into sorted-ascending t[0..K-1].
__device__ __forceinline__ void insert8s(float (&t)[K], float u) {
    #pragma unroll
    for (int k = 0; k < K; k++) {
        float lo = fminf(t[k], u);
        u = fmaxf(t[k], u);
        t[k] = lo;
    }
}

// ---------------------------------------------------------------------------
// Kernel 1: pack candidates, components pre-duplicated for f32x2 math
// ---------------------------------------------------------------------------
__global__ void prep_kernel(const float* __restrict__ in) {
    int idx = blockIdx.x * blockDim.x + threadIdx.x;   // [0, TOTQ)
    if (idx >= TOTQ) return;
    int b = idx / NPIX;
    int i = idx - b * NPIX;
    const float* base = in + (size_t)b * 3 * NPIX;
    float x = base[i];
    float y = base[NPIX + i];
    float z = base[2 * NPIX + i];
    float s = x * x + y * y + z * z;
    float mx = -2.0f * x, my = -2.0f * y, mz = -2.0f * z;
    g_cand2[2 * idx]     = make_ulonglong2(pack2(mx, mx), pack2(my, my));
    g_cand2[2 * idx + 1] = make_ulonglong2(pack2(mz, mz), pack2(s, s));
}

// ---------------------------------------------------------------------------
// Kernel 2 (phase 1): top-8 over a strided sample subchunk -> score partials
// ---------------------------------------------------------------------------
__global__ void __launch_bounds__(NTHR)
thresh_topk(const float* __restrict__ in) {
    __shared__ ulonglong2 sh[SSZ * 2];   // 288 * 32B = 9216 B

    int bid = blockIdx.x;                // [0, B*NQG*NSC) = [0,144)
    int sc  = bid & (NSC - 1);
    int qg  = (bid >> 2) % NQG;
    int b   = bid / (NQG * NSC);

    for (int i = threadIdx.x; i < SSZ * 2; i += NTHR) {
        int j = i >> 1, r = i & 1;
        sh[i] = g_cand2[(size_t)(b * NPIX + (sc * SSZ + j) * SSTRIDE) * 2 + r];
    }

    int q0 = qg * QPB + threadIdx.x;
    int q1 = q0 + NTHR;
    const float* base = in + (size_t)b * 3 * NPIX;
    float ax = base[q0], ay = base[NPIX + q0], az = base[2 * NPIX + q0];
    float bx = base[q1], by = base[NPIX + q1], bz = base[2 * NPIX + q1];
    u64 QX = pack2(ax, bx), QY = pack2(ay, by), QZ = pack2(az, bz);

    float t0[K], t1[K];
    #pragma unroll
    for (int k = 0; k < K; k++) { t0[k] = 3.0e30f; t1[k] = 3.0e30f; }

    __syncthreads();

    // small sample: conditional scalar inserts (branch hot early, cools fast)
    #pragma unroll 2
    for (int j = 0; j < SSZ; j++) {
        ulonglong2 p0 = sh[2 * j];
        ulonglong2 p1 = sh[2 * j + 1];
        u64 t = fma2(QZ, p1.x, p1.y);
        t = fma2(QY, p0.y, t);
        t = fma2(QX, p0.x, t);
        float2 d = unpack2(t);
        if (d.x < t0[K - 1]) insert8s(t0, d.x);
        if (d.y < t1[K - 1]) insert8s(t1, d.y);
    }

    int gq0 = b * NPIX + q0;
    int gq1 = b * NPIX + q1;
    #pragma unroll
    for (int k = 0; k < K; k++) {
        g_tpart[sc * K + k][gq0] = t0[k];
        g_tpart[sc * K + k][gq1] = t1[k];
    }
}

// ---------------------------------------------------------------------------
// Kernel 3 (phase 1.5): merge NSC score partials -> per-query threshold
// ---------------------------------------------------------------------------
__global__ void __launch_bounds__(NTHR)
thresh_merge() {
    int q = blockIdx.x * blockDim.x + threadIdx.x;   // [0, TOTQ)
    float t[K];
    #pragma unroll
    for (int k = 0; k < K; k++) t[k] = 3.0e30f;
    #pragma unroll
    for (int j = 0; j < NSC * K; j++) {
        float u = g_tpart[j][q];
        if (u < t[K - 1]) insert8s(t, u);
    }
    // strict-< gate downstream must admit d == T  ->  open the bound one ulp
    g_thr[q] = nextafterf(t[K - 1], 3.4e38f);
}

// ---------------------------------------------------------------------------
// Kernel 4 (phase 2): full chunked scan; top-8 initialized at threshold
// ---------------------------------------------------------------------------
__global__ void __launch_bounds__(NTHR)
topk_kernel(const float* __restrict__ in) {
    __shared__ ulonglong2 sh[CHUNK * 2];   // 1152 * 32B = 36864 B

    int bid = blockIdx.x;                // [0, B*NQG*NCHUNK) = [0,288)
    int c   = bid & (NCHUNK - 1);
    int qg  = (bid >> 3) % NQG;
    int b   = bid / (NQG * NCHUNK);

    const ulonglong2* cand = g_cand2 + (size_t)(b * NPIX + c * CHUNK) * 2;
    for (int i = threadIdx.x; i < CHUNK * 2; i += NTHR) sh[i] = cand[i];

    int q0 = qg * QPB + threadIdx.x;
    int q1 = q0 + NTHR;
    int gq0 = b * NPIX + q0;
    int gq1 = b * NPIX + q1;
    const float* base = in + (size_t)b * 3 * NPIX;
    float ax = base[q0], ay = base[NPIX + q0], az = base[2 * NPIX + q0];
    float bx = base[q1], by = base[NPIX + q1], bz = base[2 * NPIX + q1];
    u64 QX = pack2(ax, bx), QY = pack2(ay, by), QZ = pack2(az, bz);

    float T0 = g_thr[gq0];
    float T1 = g_thr[gq1];
    float t0[K], t1[K];
    #pragma unroll
    for (int k = 0; k < K; k++) { t0[k] = T0; t1[k] = T1; }
    float m0 = T0, m1 = T1;          // live copies of current maxima

    __syncthreads();

    #pragma unroll 4
    for (int j = 0; j < CHUNK; j++) {
        ulonglong2 p0 = sh[2 * j];
        ulonglong2 p1 = sh[2 * j + 1];
        u64 t = fma2(QZ, p1.x, p1.y);
        t = fma2(QY, p0.y, t);
        t = fma2(QX, p0.x, t);
        float2 d = unpack2(t);
        if (d.x < m0 || d.y < m1) {      // rare, threshold-gated
            if (d.x < m0) { insert8s(t0, d.x); m0 = t0[K - 1]; }
            if (d.y < m1) { insert8s(t1, d.y); m1 = t1[K - 1]; }
        }
    }

    float q2a = fmaf(ax, ax, fmaf(ay, ay, az * az));
    float q2b = fmaf(bx, bx, fmaf(by, by, bz * bz));

    #pragma unroll
    for (int k = 0; k < K; k++) {
        g_part[c * K + k][gq0] = t0[k] + q2a;   // coalesced across threads
        g_part[c * K + k][gq1] = t1[k] + q2b;
    }
}

// ---------------------------------------------------------------------------
// Kernel 5: merge NCHUNK partials -> per-query sum of sqrt d; fused final
// reduction via last-block ticket. Smallest element = self distance -> drop.
// ---------------------------------------------------------------------------
__global__ void __launch_bounds__(NTHR)
merge_reduce(float* __restrict__ out) {
    __shared__ float red[NTHR];
    __shared__ int islast;
    int q = blockIdx.x * NTHR + threadIdx.x;   // [0, TOTQ)

    float t[K];
    #pragma unroll
    for (int k = 0; k < K; k++) t[k] = 3.0e30f;

    #pragma unroll
    for (int j = 0; j < NCHUNK * K; j++) {
        float v = g_part[j][q];
        if (v < t[K - 1]) insert8s(t, v);
    }

    // t[0] is the self-distance (reference value: exactly 0) -> contribute 0.
    float s = 0.0f;
    #pragma unroll
    for (int k = 1; k < K; k++) s += sqrtf(fmaxf(t[k], 0.0f));

    red[threadIdx.x] = s;
    __syncthreads();
    #pragma unroll
    for (int w = NTHR / 2; w > 0; w >>= 1) {
        if (threadIdx.x < w) red[threadIdx.x] += red[threadIdx.x + w];
        __syncthreads();
    }
    if (threadIdx.x == 0) {
        g_bsum[blockIdx.x] = red[0];
        __threadfence();
        unsigned r = atomicAdd(&g_ticket, 1u);
        islast = (r == (unsigned)(gridDim.x - 1));
    }
    __syncthreads();

    if (islast) {
        float v = (threadIdx.x < NMERGE) ? __ldcg(&g_bsum[threadIdx.x]) : 0.0f;
        red[threadIdx.x] = v;
        __syncthreads();
        #pragma unroll
        for (int w = NTHR / 2; w > 0; w >>= 1) {
            if (threadIdx.x < w) red[threadIdx.x] += red[threadIdx.x + w];
            __syncthreads();
        }
        if (threadIdx.x == 0) {
            out[0] = -red[0] / (float)(TOTQ * K);
            g_ticket = 0;    // reset for next graph replay
        }
    }
}

extern "C" void kernel_launch(void* const* d_in, const int* in_sizes, int n_in,
                              void* d_out, int out_size) {
    const float* in = (const float*)d_in[0];
    float* out = (float*)d_out;

    prep_kernel<<<(TOTQ + NTHR - 1) / NTHR, NTHR>>>(in);
    thresh_topk<<<B * NQG * NSC, NTHR>>>(in);
    thresh_merge<<<TOTQ / NTHR, NTHR>>>();
    topk_kernel<<<B * NQG * NCHUNK, NTHR>>>(in);
    merge_reduce<<<NMERGE, NTHR>>>(out);
}